// round 9
// baseline (speedup 1.0000x reference)
#include <cuda_runtime.h>
#include <cuda_fp16.h>
#include <cstdint>

#define BB 16
#define LQ 256
#define LK 4096

typedef unsigned long long ull;

// ---------------- device scratch (no allocation allowed) --------------------
__device__ __align__(16) __half g_qh [BB * LQ * 64];          // Q proj, f16, pre-scaled
__device__ __align__(16) __half g_kh [(long)BB * LK * 64];    // K proj, f16
__device__ __align__(16) __half g_wth[(long)BB * 64 * LK];    // Wt[b][d][kk] = [m*v | m]
__device__ __align__(16) float  g_part[(long)2 * 16 * 4 * 64 * 256]; // [ks][b][qt][q][256]

// ---------------- helpers ----------------------------------------------------
__device__ __forceinline__ uint32_t smem_u32(const void* p) {
    uint32_t a;
    asm("{ .reg .u64 t; cvta.to.shared.u64 t, %1; cvt.u32.u64 %0, t; }" : "=r"(a) : "l"(p));
    return a;
}
__device__ __forceinline__ uint32_t f16x2_of(float lo, float hi) {
    uint32_t r; asm("cvt.rn.f16x2.f32 %0, %1, %2;" : "=r"(r) : "f"(hi), "f"(lo)); return r;
}
__device__ __forceinline__ uint32_t ex2x2(uint32_t a) {
    uint32_t r; asm("ex2.approx.f16x2 %0, %1;" : "=r"(r) : "r"(a)); return r;
}
__device__ __forceinline__ void cp16(uint32_t dst, const void* src) {
    asm volatile("cp.async.ca.shared.global [%0], [%1], 16;" :: "r"(dst), "l"(src));
}
#define CP_COMMIT() asm volatile("cp.async.commit_group;" ::: "memory")
#define CP_WAIT(n)  asm volatile("cp.async.wait_group %0;" :: "n"(n) : "memory")

__device__ __forceinline__ void ldsm_x4(uint32_t* r, uint32_t a) {
    asm volatile("ldmatrix.sync.aligned.m8n8.x4.shared.b16 {%0,%1,%2,%3}, [%4];"
                 : "=r"(r[0]), "=r"(r[1]), "=r"(r[2]), "=r"(r[3]) : "r"(a));
}
__device__ __forceinline__ void mma_acc(float* d, const uint32_t* a, const uint32_t* b) {
    asm volatile("mma.sync.aligned.m16n8k16.row.col.f32.f16.f16.f32 "
        "{%0,%1,%2,%3}, {%4,%5,%6,%7}, {%8,%9}, {%0,%1,%2,%3};"
        : "+f"(d[0]), "+f"(d[1]), "+f"(d[2]), "+f"(d[3])
        : "r"(a[0]), "r"(a[1]), "r"(a[2]), "r"(a[3]), "r"(b[0]), "r"(b[1]));
}
__device__ __forceinline__ void mma_zro(float* d, const uint32_t* a, const uint32_t* b) {
    asm volatile("mma.sync.aligned.m16n8k16.row.col.f32.f16.f16.f32 "
        "{%0,%1,%2,%3}, {%4,%5,%6,%7}, {%8,%9}, {%10,%10,%10,%10};"
        : "=f"(d[0]), "=f"(d[1]), "=f"(d[2]), "=f"(d[3])
        : "r"(a[0]), "r"(a[1]), "r"(a[2]), "r"(a[3]), "r"(b[0]), "r"(b[1]), "f"(0.0f));
}

#define QSCALE 0.36067376022224085f   // 0.25 * log2(e)
#define SWZ(o) ((o) ^ (((o) >> 3) & 0x70))

// ---------------- fused prep ------------------------------------------------
// grid 1088: [0,64) q-proj (FFMA), [64,576) k-proj (HMMA hi/lo), [576,1088) wt
__global__ void __launch_bounds__(256) prep_kernel(
    const float* __restrict__ qin, const float* __restrict__ kin,
    const float* __restrict__ v, const int* __restrict__ m,
    const float* __restrict__ Wq, const float* __restrict__ bq,
    const float* __restrict__ Wk, const float* __restrict__ bk)
{
    extern __shared__ __align__(16) char psm[];
    const int bid = blockIdx.x, t = threadIdx.x;

    if (bid < 64) {
        // ---- q projection (small): FFMA, scale into log2 domain ----
        float* Wsh = (float*)psm;                 // [64*64]
        float* Ish = (float*)(psm + 16384);       // [64*68]
        const long row0 = (long)bid * 64;
        const float4* ing = (const float4*)(qin + row0 * 64);
        #pragma unroll
        for (int i = t; i < 1024; i += 256) ((float4*)Wsh)[i] = ((const float4*)Wq)[i];
        #pragma unroll
        for (int i = t; i < 1024; i += 256) {
            int rr = i >> 4, c = i & 15;
            *(float4*)&Ish[rr * 68 + c * 4] = ing[i];
        }
        __syncthreads();
        const int e0 = (t & 15) * 4;
        const int rb = (t >> 4) * 4;
        float4 bv = *(const float4*)&bq[e0];
        float4 a0 = bv, a1 = bv, a2 = bv, a3 = bv;
        #pragma unroll 8
        for (int j = 0; j < 64; j++) {
            float4 wv = *(const float4*)&Wsh[j * 64 + e0];
            float i0 = Ish[(rb + 0) * 68 + j];
            float i1 = Ish[(rb + 1) * 68 + j];
            float i2 = Ish[(rb + 2) * 68 + j];
            float i3 = Ish[(rb + 3) * 68 + j];
            a0.x += i0 * wv.x; a0.y += i0 * wv.y; a0.z += i0 * wv.z; a0.w += i0 * wv.w;
            a1.x += i1 * wv.x; a1.y += i1 * wv.y; a1.z += i1 * wv.z; a1.w += i1 * wv.w;
            a2.x += i2 * wv.x; a2.y += i2 * wv.y; a2.z += i2 * wv.z; a2.w += i2 * wv.w;
            a3.x += i3 * wv.x; a3.y += i3 * wv.y; a3.z += i3 * wv.z; a3.w += i3 * wv.w;
        }
        float4 aa[4] = {a0, a1, a2, a3};
        #pragma unroll
        for (int r = 0; r < 4; r++) {
            uint2 u;
            u.x = f16x2_of(aa[r].x * QSCALE, aa[r].y * QSCALE);
            u.y = f16x2_of(aa[r].z * QSCALE, aa[r].w * QSCALE);
            *(uint2*)&g_qh[(row0 + rb + r) * 64 + e0] = u;
        }
    } else if (bid < 576) {
        // ---- k projection via HMMA, fp32-emulated with hi/lo f16 split ----
        // SMEM: Bt-hi @0 (8KB), Bt-lo @8192, Wsh f32 64x65 @16384,
        //       A-hi @33792 (16KB), A-lo @50176
        __half* bth = (__half*)psm;
        __half* btl = (__half*)(psm + 8192);
        float*  wsh = (float*)(psm + 16384);
        char*   ah  = psm + 33792;
        char*   al  = psm + 50176;
        const uint32_t sbth = smem_u32(bth), sah = smem_u32(ah);

        const long row0 = (long)(bid - 64) * 128;
        // W coalesced -> wsh[j][e] padded 65
        #pragma unroll
        for (int i = t; i < 4096; i += 256)
            wsh[(i >> 6) * 65 + (i & 63)] = Wk[i];
        // key rows -> A hi/lo f16, SW128 rows of 128B
        {
            const float4* kg4 = (const float4*)(kin + row0 * 64);
            #pragma unroll
            for (int i = t; i < 2048; i += 256) {
                float4 vv = kg4[i];
                uint2 hi, lo;
                hi.x = f16x2_of(vv.x, vv.y); hi.y = f16x2_of(vv.z, vv.w);
                __half2 h0 = *(__half2*)&hi.x, h1 = *(__half2*)&hi.y;
                lo.x = f16x2_of(vv.x - __half2float(h0.x), vv.y - __half2float(h0.y));
                lo.y = f16x2_of(vv.z - __half2float(h1.x), vv.w - __half2float(h1.y));
                uint32_t off = (uint32_t)(i >> 4) * 128 + (i & 15) * 8;
                off = SWZ(off);
                *(uint2*)(ah + off) = hi;
                *(uint2*)(al + off) = lo;
            }
        }
        __syncthreads();
        // transpose W -> Bt[e][j] hi/lo (conflict-free via 65-pad reads)
        #pragma unroll
        for (int i = t; i < 4096; i += 256) {
            int j = i & 63, e = i >> 6;
            float wv = wsh[j * 65 + e];
            __half whi = __float2half(wv);
            uint32_t off = SWZ((uint32_t)e * 128 + j * 2);
            *(__half*)((char*)bth + off) = whi;
            *(__half*)((char*)btl + off) = __float2half(wv - __half2float(whi));
        }
        __syncthreads();

        const int l = t & 31, wid = t >> 5;
        const int li = l & 7, m4 = l >> 3, quad = l >> 3;
        // A frags: 4 kt, hi+lo
        uint32_t Ah[4][4], Al[4][4];
        {
            const uint32_t arow = (uint32_t)(wid * 16 + (quad & 1) * 8 + li) * 128;
            #pragma unroll
            for (int kt = 0; kt < 4; kt++) {
                uint32_t acol = ((uint32_t)(kt * 32 + (quad >> 1) * 16)) ^ ((uint32_t)li << 4);
                ldsm_x4(Ah[kt], sah + arow + acol);
                ldsm_x4(Al[kt], sah + 16384 + arow + acol);
            }
        }
        float O2[8][4];
        #pragma unroll
        for (int nt = 0; nt < 8; nt++)
            #pragma unroll
            for (int i = 0; i < 4; i++) O2[nt][i] = 0.0f;

        const uint32_t brow = (uint32_t)((m4 >> 1) * 8 + li) * 128;
        #pragma unroll
        for (int p = 0; p < 4; p++) {
            #pragma unroll
            for (int kt = 0; kt < 4; kt++) {
                uint32_t bcol = ((uint32_t)(kt * 32 + (m4 & 1) * 16)) ^ ((uint32_t)li << 4);
                uint32_t addr = sbth + (uint32_t)p * 2048 + brow + bcol;
                uint32_t bh[4], bl[4];
                ldsm_x4(bh, addr);
                ldsm_x4(bl, addr + 8192);
                mma_acc(O2[2 * p],     Ah[kt], bh);
                mma_acc(O2[2 * p + 1], Ah[kt], bh + 2);
                mma_acc(O2[2 * p],     Ah[kt], bl);
                mma_acc(O2[2 * p + 1], Ah[kt], bl + 2);
                mma_acc(O2[2 * p],     Al[kt], bh);
                mma_acc(O2[2 * p + 1], Al[kt], bh + 2);
            }
        }
        // epilogue: + bias, cvt f16, store
        #pragma unroll
        for (int nt = 0; nt < 8; nt++) {
            int e = nt * 8 + 2 * (l & 3);
            float b0 = bk[e], b1 = bk[e + 1];
            long r0 = row0 + wid * 16 + (l >> 2);
            *(uint32_t*)&g_kh[r0 * 64 + e]       = f16x2_of(O2[nt][0] + b0, O2[nt][1] + b1);
            *(uint32_t*)&g_kh[(r0 + 8) * 64 + e] = f16x2_of(O2[nt][2] + b0, O2[nt][3] + b1);
        }
    } else {
        // ---- Wt build: g_wth[b][d][kk] = [m*v | m] (f16) ----
        __half* Wsm = (__half*)psm;               // [64][144]
        const int id = bid - 576;
        const int b = id >> 5, kt = id & 31;
        const long base = ((long)b * LK + kt * 128) * 32;
        for (int i = t; i < 4096; i += 256) {
            int kk = i >> 5, d = i & 31;
            float mv = (float)m[base + i];
            float vv = v[base + i];
            Wsm[d * 144 + kk]        = __float2half(mv * vv);
            Wsm[(d + 32) * 144 + kk] = __float2half(mv);
        }
        __syncthreads();
        for (int i = t; i < 1024; i += 256) {
            int row = i >> 4, c = i & 15;
            *(uint4*)(g_wth + ((long)b * 64 + row) * LK + kt * 128 + c * 8) =
                *(uint4*)&Wsm[row * 144 + c * 8];
        }
    }
}

// ---------------- main fused attention: 64q per CTA, Lk split 2 -------------
// grid (4 qt, 16 b, 2 ks) = 128 CTAs, 256 thr = 8 warps: warp = (h = w&3, s = w>>2).
// Per CTA: 64 q rows, kk window [ks*2048, +2048) = 32 chunks of 64.
// SMEM: Q 8KB @0; stage c&3: K 8KB @8192+16384*(c&3), W @+8192.
// Writes [num|den] partials (fp32) to g_part; fin kernel reduces.
__global__ void __launch_bounds__(256, 1) attn_kernel()
{
    extern __shared__ __align__(16) char smraw[];
    const uint32_t base = smem_u32(smraw);
    const uint32_t sb = (base + 1023) & ~1023u;
    char* shb = smraw + (sb - base);

    const int t = threadIdx.x, l = t & 31, w = t >> 5;
    const int h = w & 3, s = w >> 2;
    const int qt = blockIdx.x, b = blockIdx.y, ks = blockIdx.z;
    const int kk0g = ks * 2048;

    const char*   qg = (const char*)(g_qh + ((long)(b * LQ + qt * 64)) * 64);
    const __half* kg = g_kh  + (long)b * LK * 64;
    const __half* wg = g_wth + (long)b * 64 * LK;

    auto issue = [&](int c) {
        const uint32_t KB = sb + 8192 + (uint32_t)(c & 3) * 16384, WB = KB + 8192;
        const int kk0 = kk0g + c * 64;
        const char* ks8 = (const char*)(kg + (long)kk0 * 64);
        #pragma unroll
        for (int i = t; i < 1024; i += 256) {
            if (i < 512) {
                uint32_t off = i * 16;
                cp16(KB + SWZ(off), ks8 + off);
            } else {
                int j = i - 512;
                uint32_t off = j * 16;
                cp16(WB + SWZ(off), (const char*)(wg + (long)(j >> 3) * LK + kk0) + (j & 7) * 16);
            }
        }
    };

    // group 0: Q + chunk 0; groups 1,2: chunks 1,2
    #pragma unroll
    for (int i = t; i < 512; i += 256) {
        uint32_t off = i * 16;
        cp16(sb + SWZ(off), qg + off);
    }
    issue(0); CP_COMMIT();
    issue(1); CP_COMMIT();
    issue(2); CP_COMMIT();

    const int li = l & 7, m4 = l >> 3;
    const uint32_t kRowBase = (uint32_t)(s * 32 + (m4 >> 1) * 8 + li) * 128
                            + (((uint32_t)(h * 32 + (m4 & 1) * 16)) ^ ((uint32_t)li << 4));
    const uint32_t wRow = (uint32_t)((m4 >> 1) * 8 + li) * 128;
    uint32_t wCol[2];
    #pragma unroll
    for (int j = 0; j < 2; j++)
        wCol[j] = ((uint32_t)(s * 64 + j * 32 + (m4 & 1) * 16)) ^ ((uint32_t)li << 4);

    CP_WAIT(2);
    __syncthreads();

    // Q A-frags: 4 m-tiles (64 q rows)
    uint32_t aq[4][4];
    {
        const int quad = l >> 3;
        #pragma unroll
        for (int mt = 0; mt < 4; mt++) {
            const uint32_t arow = (uint32_t)(mt * 16 + (quad & 1) * 8 + li) * 128;
            const uint32_t acol = ((uint32_t)(h * 32 + (quad >> 1) * 16)) ^ ((uint32_t)li << 4);
            ldsm_x4(aq[mt], sb + arow + acol);
        }
    }

    float O[4][8][4];
    #pragma unroll
    for (int mt = 0; mt < 4; mt++)
        #pragma unroll
        for (int nt = 0; nt < 8; nt++)
            #pragma unroll
            for (int i = 0; i < 4; i++) O[mt][nt][i] = 0.0f;

    for (int c = 0; c < 32; c++) {
        if (c) { CP_WAIT(2); __syncthreads(); }
        if (c + 3 < 32) issue(c + 3);
        CP_COMMIT();

        const uint32_t KBp = sb + 8192 + (uint32_t)(c & 3) * 16384, WBp = KBp + 8192;

        // GEMM1 + exp: warp covers kk [s*32, s*32+32) of this chunk
        uint32_t E[4][2][4];
        #pragma unroll
        for (int j = 0; j < 2; j++) {
            uint32_t kf[4];
            ldsm_x4(kf, KBp + kRowBase + (uint32_t)j * 2048);
            #pragma unroll
            for (int mt = 0; mt < 4; mt++) {
                float s0[4], s1[4];
                mma_zro(s0, aq[mt], kf);
                mma_zro(s1, aq[mt], kf + 2);
                E[mt][j][0] = ex2x2(f16x2_of(s0[0], s0[1]));
                E[mt][j][1] = ex2x2(f16x2_of(s0[2], s0[3]));
                E[mt][j][2] = ex2x2(f16x2_of(s1[0], s1[1]));
                E[mt][j][3] = ex2x2(f16x2_of(s1[2], s1[3]));
            }
        }

        // GEMM2: O += E . Wt^T over this warp's 32 kk
        #pragma unroll
        for (int j = 0; j < 2; j++) {
            #pragma unroll
            for (int p = 0; p < 4; p++) {
                uint32_t wf[4];
                ldsm_x4(wf, WBp + wRow + (uint32_t)p * 2048 + wCol[j]);
                #pragma unroll
                for (int mt = 0; mt < 4; mt++) {
                    mma_acc(O[mt][2 * p],     E[mt][j], wf);
                    mma_acc(O[mt][2 * p + 1], E[mt][j], wf + 2);
                }
            }
        }
    }
    __syncthreads();   // all warps done with stages before reuse as reduce buffer

    // ---- reduce kk-halves (s=1 -> SMEM, s=0 adds), write partials ----------
    float* red = (float*)(shb + 8192);   // [h][q 64][col 64], xor-swizzled
    #define RIDX(q, col) ((q) * 64 + ((col) ^ (((q) & 3) << 3)))
    if (s == 1) {
        #pragma unroll
        for (int mt = 0; mt < 4; mt++)
            #pragma unroll
            for (int nt = 0; nt < 8; nt++)
                #pragma unroll
                for (int i = 0; i < 4; i++) {
                    int q = mt * 16 + (l >> 2) + ((i >> 1) & 1) * 8;
                    int col = nt * 8 + 2 * (l & 3) + (i & 1);
                    red[h * 4096 + RIDX(q, col)] = O[mt][nt][i];
                }
    }
    __syncthreads();
    if (s == 0) {
        float* P = g_part + ((((long)ks * 16 + b) * 4 + qt) << 14);
        #pragma unroll
        for (int mt = 0; mt < 4; mt++)
            #pragma unroll
            for (int nt = 0; nt < 8; nt++) {
                #pragma unroll
                for (int i = 0; i < 4; i++) {
                    int q = mt * 16 + (l >> 2) + ((i >> 1) & 1) * 8;
                    int col = nt * 8 + 2 * (l & 3) + (i & 1);
                    O[mt][nt][i] += red[h * 4096 + RIDX(q, col)];
                }
                int q0 = mt * 16 + (l >> 2);
                int col = h * 64 + nt * 8 + 2 * (l & 3);
                *(float2*)(P + (long)q0 * 256 + col)       = make_float2(O[mt][nt][0], O[mt][nt][1]);
                *(float2*)(P + (long)(q0 + 8) * 256 + col) = make_float2(O[mt][nt][2], O[mt][nt][3]);
            }
    }
}

// ---------------- finalize: reduce ks, divide, @Wo + bo ---------------------
__global__ void __launch_bounds__(256) fin_kernel(
    const float* __restrict__ Wo, const float* __restrict__ bo, float* __restrict__ out)
{
    __shared__ __align__(16) float X[64 * 132];
    const int t = threadIdx.x;
    const int b = blockIdx.x >> 2, qt = blockIdx.x & 3;

    const float* P0 = g_part + ((((long)0 * 16 + b) * 4 + qt) << 14);
    const float* P1 = g_part + ((((long)1 * 16 + b) * 4 + qt) << 14);

    #pragma unroll
    for (int f4 = t; f4 < 2048; f4 += 256) {
        int q = f4 >> 5, c4 = f4 & 31;
        int hh = c4 >> 3, d4 = c4 & 7;
        long o = (long)q * 256 + hh * 64 + d4 * 4;
        float4 n0 = *(const float4*)(P0 + o);
        float4 n1 = *(const float4*)(P1 + o);
        float4 d0 = *(const float4*)(P0 + o + 32);
        float4 d1 = *(const float4*)(P1 + o + 32);
        float* xr = X + q * 132 + hh * 32 + d4 * 4;
        xr[0] = __fdividef(n0.x + n1.x, d0.x + d1.x);
        xr[1] = __fdividef(n0.y + n1.y, d0.y + d1.y);
        xr[2] = __fdividef(n0.z + n1.z, d0.z + d1.z);
        xr[3] = __fdividef(n0.w + n1.w, d0.w + d1.w);
    }
    __syncthreads();

    const int q = t >> 2, lat0 = (t & 3) * 8;
    float acc[8];
    #pragma unroll
    for (int i = 0; i < 8; i++) acc[i] = bo[lat0 + i];
    #pragma unroll 8
    for (int j = 0; j < 128; j++) {
        float xv = X[q * 132 + j];
        float4 w0 = *(const float4*)&Wo[j * 32 + lat0];
        float4 w1 = *(const float4*)&Wo[j * 32 + lat0 + 4];
        acc[0] += xv * w0.x; acc[1] += xv * w0.y; acc[2] += xv * w0.z; acc[3] += xv * w0.w;
        acc[4] += xv * w1.x; acc[5] += xv * w1.y; acc[6] += xv * w1.z; acc[7] += xv * w1.w;
    }
    float* op = out + ((long)(b * LQ + qt * 64 + q)) * 32 + lat0;
    *(float4*)op       = make_float4(acc[0], acc[1], acc[2], acc[3]);
    *(float4*)(op + 4) = make_float4(acc[4], acc[5], acc[6], acc[7]);
}

// ---------------- launch ------------------------------------------------------
extern "C" void kernel_launch(void* const* d_in, const int* in_sizes, int n_in,
                              void* d_out, int out_size)
{
    const float* query = (const float*)d_in[0];
    const float* key   = (const float*)d_in[1];
    const float* value = (const float*)d_in[2];
    const int*   mask  = (const int*)  d_in[3];
    const float* Wq    = (const float*)d_in[4];
    const float* bq    = (const float*)d_in[5];
    const float* Wk    = (const float*)d_in[6];
    const float* bk    = (const float*)d_in[7];
    const float* Wo    = (const float*)d_in[8];
    const float* bo    = (const float*)d_in[9];
    float* out = (float*)d_out;
    (void)in_sizes; (void)n_in; (void)out_size;

    const int prep_smem = 67584;
    const int attn_smem = 8192 + 4 * 16384 + 1024;
    cudaFuncSetAttribute(prep_kernel, cudaFuncAttributeMaxDynamicSharedMemorySize, prep_smem);
    cudaFuncSetAttribute(attn_kernel, cudaFuncAttributeMaxDynamicSharedMemorySize, attn_smem);

    prep_kernel<<<1088, 256, prep_smem>>>(query, key, value, mask, Wq, bq, Wk, bk);
    dim3 grid(4, BB, 2);
    attn_kernel<<<grid, 256, attn_smem>>>();
    fin_kernel<<<64, 256>>>(Wo, bo, out);
}